// round 15
// baseline (speedup 1.0000x reference)
#include <cuda_runtime.h>
#include <math.h>

#define HH 1024
#define WW 1024
#define NB 2
#define KK 24   // number of SOCS kernels
#define KD 35   // kernel spatial size / cropped spectrum size
#define FC 17   // center offset: frequency f = index - 17
#define U2 18   // u-pairs
#define UH 9    // u-pairs per thread-half
#define NS 128  // x-sample points (x = 8j)
#define NDV 69  // dv = -34..34
#define NBLK 148

// ---------------- scratch (static __device__, no allocation) ----------------
__device__ float2 g_cs[1024];                 // e^{+2pi i t/1024}
__device__ float2 g_T[NB][KD][HH];            // row DFT, transposed (j2-major)
__device__ float2 g_spec[NB][KD][KD];         // cropped spectrum (1/(H*W) folded)
__device__ float  g_Dj[NB][2][KD][NS][2];     // D at 128 x-samples (atomic accum)
__device__ float2 g_D[NB][2][KD][WW];         // cross-spectral density over du
__device__ unsigned g_barcnt;                 // grid barrier (zero-init; self-resetting)
__device__ unsigned g_bargen;                 // monotonic generation (replay-safe)

// ---------------- f32x2 packed helpers (Blackwell) ----------------
__device__ __forceinline__ unsigned long long pk2(float lo, float hi) {
    unsigned long long r;
    asm("mov.b64 %0, {%1, %2};" : "=l"(r) : "f"(lo), "f"(hi));
    return r;
}
__device__ __forceinline__ unsigned long long fma2(unsigned long long a, unsigned long long b, unsigned long long c) {
    unsigned long long d;
    asm("fma.rn.f32x2 %0, %1, %2, %3;" : "=l"(d) : "l"(a), "l"(b), "l"(c));
    return d;
}
__device__ __forceinline__ void upk2(unsigned long long v, float& lo, float& hi) {
    asm("mov.b64 {%0, %1}, %2;" : "=f"(lo), "=f"(hi) : "l"(v));
}
__device__ __forceinline__ float2 twd(int t) {
    float s, c;
    sincospif((float)(t & 1023) / 512.0f, &s, &c);
    return make_float2(c, s);
}

// ---------------- grid barrier: all 148 blocks resident (1 block/SM) ----------------
__device__ __forceinline__ void grid_bar() {
    __syncthreads();
    if (threadIdx.x == 0) {
        __threadfence();                                  // release prior global writes
        unsigned gen = *((volatile unsigned*)&g_bargen);  // read BEFORE arriving (safe)
        unsigned old = atomicAdd(&g_barcnt, 1u);
        if (old == NBLK - 1u) {
            *((volatile unsigned*)&g_barcnt) = 0u;        // reset for next barrier
            __threadfence();
            atomicAdd(&g_bargen, 1u);                     // flip generation
        } else {
            while (*((volatile unsigned*)&g_bargen) == gen) __nanosleep(64);
        }
        __threadfence();                                  // acquire
    }
    __syncthreads();
}

// ---------------- Gram helper (sampled) ----------------
template <int DU0, int DW>
__device__ __forceinline__ void gram_s(const unsigned long long* Ru, float s,
                                       float* dj, int j) {
    unsigned long long accX[DW], accY[DW];
    #pragma unroll
    for (int q = 0; q < DW; q++) { accX[q] = 0ull; accY[q] = 0ull; }
    #pragma unroll
    for (int u = 0; u < KD; u++) {
        float rx, ry;
        upk2(Ru[u], rx, ry);
        float ax = s * rx, ay = s * ry;
        unsigned long long axy  = pk2(ax, ay);
        unsigned long long aynx = pk2(ay, -ax);
        #pragma unroll
        for (int q = 0; q < DW; q++) {
            if (DU0 + q <= u) {
                unsigned long long bxy = Ru[u - DU0 - q];
                accX[q] = fma2(axy,  bxy, accX[q]);
                accY[q] = fma2(aynx, bxy, accY[q]);
            }
        }
    }
    #pragma unroll
    for (int q = 0; q < DW; q++) {
        float x0, x1, y0, y1;
        upk2(accX[q], x0, x1);
        upk2(accY[q], y0, y1);
        atomicAdd(&dj[(DU0 + q) * NS * 2 + j * 2 + 0], x0 + x1);
        atomicAdd(&dj[(DU0 + q) * NS * 2 + j * 2 + 1], y0 + y1);
    }
}

// ---------------- the whole pipeline in one kernel ----------------
__global__ void __launch_bounds__(256, 1) k_all(
    const float* __restrict__ mask,
    const float* __restrict__ fr, const float* __restrict__ fi,
    const float* __restrict__ dr, const float* __restrict__ di,
    const float* __restrict__ fs, const float* __restrict__ ds,
    float* __restrict__ out)
{
    __shared__ __align__(16) char smbuf[46080];
    int tid = threadIdx.x;
    int bid = blockIdx.x;

    // ===== phase 0: zero g_Dj + twiddle table + rowdft =====
    if (bid < 140) {                          // 140*256 = 35840 floats exactly
        float* djf = &g_Dj[0][0][0][0][0];
        djf[bid*256 + tid] = 0.f;
    }
    if (bid == NBLK-1) {
        for (int t = tid; t < 1024; t += 256) {
            float s, c;
            sincospif((float)t / 512.0f, &s, &c);
            g_cs[t] = make_float2(c, s);
        }
    }
    {
        float (*raw)[WW] = (float(*)[WW])smbuf;                // 24576 B
        float (*m_s)[WW] = (float(*)[WW])(smbuf + 24576);      // 16384 B
        for (int wi = bid; wi < 512; wi += NBLK) {
            int n  = wi & 1;
            int yb = wi >> 1;
            __syncthreads();                  // smem reuse across iterations
            const float* base = mask + (size_t)n * HH * WW;
            #pragma unroll
            for (int jj = 0; jj < 6; jj++) {
                int gy = yb*4 - 1 + jj;
                for (int x = tid; x < WW; x += 256)
                    raw[jj][x] = (gy >= 0 && gy < HH) ? base[(size_t)gy * WW + x] : 0.f;
            }
            __syncthreads();
            for (int x = tid; x < WW; x += 256) {
                float r0 = raw[0][x], r1 = raw[1][x], r2 = raw[2][x];
                float r3 = raw[3][x], r4 = raw[4][x], r5 = raw[5][x];
                raw[0][x] = r0 + r1 + r2;
                raw[1][x] = r1 + r2 + r3;
                raw[2][x] = r2 + r3 + r4;
                raw[3][x] = r3 + r4 + r5;
            }
            __syncthreads();
            for (int x = tid; x < WW; x += 256) {
                #pragma unroll
                for (int yy = 0; yy < 4; yy++) {
                    float s = raw[yy][x];
                    if (x > 0)    s += raw[yy][x-1];
                    if (x < WW-1) s += raw[yy][x+1];
                    float p = s * (1.0f/9.0f);
                    m_s[yy][x] = 1.0f / (1.0f + expf(-4.0f * (p - 0.5f)));
                }
            }
            __syncthreads();
            int warp = tid >> 5, lane = tid & 31;
            for (int j2 = warp; j2 < KD; j2 += 8) {
                int a = FC - j2;
                float2 t  = twd(a * lane);
                float2 st = twd(a * 32);
                unsigned long long acc[4] = {0ull, 0ull, 0ull, 0ull};
                for (int i = 0; i < 32; i++) {
                    int x = lane + 32*i;
                    unsigned long long t2 = pk2(t.x, t.y);
                    #pragma unroll
                    for (int yy = 0; yy < 4; yy++) {
                        float mv = m_s[yy][x];
                        acc[yy] = fma2(pk2(mv, mv), t2, acc[yy]);
                    }
                    float tx = t.x*st.x - t.y*st.y;
                    float ty = t.x*st.y + t.y*st.x;
                    t = make_float2(tx, ty);
                }
                #pragma unroll
                for (int yy = 0; yy < 4; yy++) {
                    float ar, ai;
                    upk2(acc[yy], ar, ai);
                    for (int o = 16; o; o >>= 1) {
                        ar += __shfl_xor_sync(0xffffffffu, ar, o);
                        ai += __shfl_xor_sync(0xffffffffu, ai, o);
                    }
                    if (lane == 0) g_T[n][j2][yb*4 + yy] = make_float2(ar, ai);
                }
            }
        }
    }
    grid_bar();

    // ===== phase 1: column DFT (70 work units) =====
    if (bid < 70) {
        float2* Ts = (float2*)smbuf;          // 8192 B
        int j2 = bid % KD, n = bid / KD;
        for (int i = tid; i < HH; i += 256) Ts[i] = g_T[n][j2][i];
        __syncthreads();
        int warp = tid >> 5, lane = tid & 31;
        const float norm = 1.0f / (1024.0f * 1024.0f);
        for (int j1 = warp; j1 < KD; j1 += 8) {
            int a = FC - j1;
            float2 t  = g_cs[(a * lane) & 1023];
            float2 st = g_cs[(a * 32)   & 1023];
            float ar = 0.f, ai = 0.f;
            for (int i = 0; i < 32; i++) {
                float2 T = Ts[lane + 32*i];
                ar += T.x*t.x - T.y*t.y;
                ai += T.x*t.y + T.y*t.x;
                float tx = t.x*st.x - t.y*st.y;
                float ty = t.x*st.y + t.y*st.x;
                t = make_float2(tx, ty);
            }
            for (int o = 16; o; o >>= 1) {
                ar += __shfl_xor_sync(0xffffffffu, ar, o);
                ai += __shfl_xor_sync(0xffffffffu, ai, o);
            }
            if (lane == 0) g_spec[n][j1][j2] = make_float2(ar * norm, ai * norm);
        }
    }
    grid_bar();

    // ===== phase 2: R-at-samples + Gram + atomic D_j (96 work units) =====
    if (bid < 96) {
        float4 (*Bs)[U2] = (float4(*)[U2])smbuf;                 // 10080 B
        float2 (*Rs)[NS] = (float2(*)[NS])(smbuf + 10240);       // 35840 B
        int k   = bid % KK;
        int nbr = bid / KK; int n = nbr >> 1, br = nbr & 1;
        const float* krp = (br == 0) ? fr : dr;
        const float* kip = (br == 0) ? fi : di;
        float s = ((br == 0) ? fs : ds)[k];
        for (int i = tid; i < KD*U2; i += 256) {
            int u2 = i / KD, v = i % KD;
            int u0 = 2*u2, u1 = u0 + 1;
            float2 A0 = g_spec[n][u0][v];
            float Kr = krp[(k*KD + u0)*KD + v];
            float Ki = kip[(k*KD + u0)*KD + v];
            float b0x = A0.x*Kr - A0.y*Ki, b0y = A0.x*Ki + A0.y*Kr;
            float b1x = 0.f, b1y = 0.f;
            if (u1 < KD) {
                float2 A1 = g_spec[n][u1][v];
                float Kr1 = krp[(k*KD + u1)*KD + v];
                float Ki1 = kip[(k*KD + u1)*KD + v];
                b1x = A1.x*Kr1 - A1.y*Ki1; b1y = A1.x*Ki1 + A1.y*Kr1;
            }
            Bs[v][u2] = make_float4(b0x, b1x, b0y, b1y);
        }
        __syncthreads();
        int j = tid & 127, h = tid >> 7;
        {
            float2 w = g_cs[(8 * j) & 1023];
            float2 t = make_float2(1.f, 0.f);
            unsigned long long aR[UH], aI[UH];
            #pragma unroll
            for (int uu = 0; uu < UH; uu++) { aR[uu] = 0ull; aI[uu] = 0ull; }
            #pragma unroll
            for (int v = 0; v < KD; v++) {
                unsigned long long pxx = pk2(t.x,  t.x);
                unsigned long long pyy = pk2(t.y,  t.y);
                unsigned long long nyy = pk2(-t.y, -t.y);
                #pragma unroll
                for (int uu = 0; uu < UH; uu++) {
                    float4 b = Bs[v][h*UH + uu];
                    unsigned long long bx = pk2(b.x, b.y);
                    unsigned long long by = pk2(b.z, b.w);
                    aR[uu] = fma2(bx, pxx, aR[uu]);
                    aR[uu] = fma2(by, nyy, aR[uu]);
                    aI[uu] = fma2(bx, pyy, aI[uu]);
                    aI[uu] = fma2(by, pxx, aI[uu]);
                }
                float tx = t.x*w.x - t.y*w.y;
                float ty = t.x*w.y + t.y*w.x;
                t = make_float2(tx, ty);
            }
            #pragma unroll
            for (int uu = 0; uu < UH; uu++) {
                int u0 = 2*(h*UH + uu);
                float r0, r1, i0, i1;
                upk2(aR[uu], r0, r1);
                upk2(aI[uu], i0, i1);
                Rs[u0][j] = make_float2(r0, i0);
                if (u0 + 1 < KD) Rs[u0+1][j] = make_float2(r1, i1);
            }
        }
        __syncthreads();
        unsigned long long Ru[KD];
        #pragma unroll
        for (int u = 0; u < KD; u++)
            Ru[u] = *reinterpret_cast<const unsigned long long*>(&Rs[u][j]);
        float* dj = &g_Dj[n][br][0][0][0];
        if (h == 0) gram_s<0, 18>(Ru, s, dj, j);
        else        gram_s<18, 17>(Ru, s, dj, j);
    }
    grid_bar();

    // ===== phase 3: Dj -> G (radix-2 in j) -> D (radix-4 in x)  (140 units) =====
    if (bid < 140) {
        float2* Ds = (float2*)smbuf;                              // 1024 B
        float2 (*Gp)[NDV] = (float2(*)[NDV])(smbuf + 1024);       // 1104 B
        float2* Gs = (float2*)(smbuf + 1024 + 1104 + 8);          // 552 B
        int du  = bid % KD;
        int nbr = bid / KD; int n = nbr >> 1, br = nbr & 1;
        if (tid < NS) {
            const float* djp = &g_Dj[n][br][du][tid][0];
            Ds[tid] = make_float2(djp[0], djp[1]);
        }
        __syncthreads();
        if (tid < 2*NDV) {
            int dvi = (tid < NDV) ? tid : tid - NDV;
            int h   = (tid < NDV) ? 0 : 1;
            int dv  = dvi - 34;
            float2 w = g_cs[(-8 * dv) & 1023];
            float2 t = make_float2(((dv & 1) && h) ? -1.f : 1.f, 0.f);
            float gr = 0.f, gi = 0.f;
            #pragma unroll
            for (int j0 = 0; j0 < 64; j0++) {
                float2 Dj = Ds[j0 + 64*h];
                gr += Dj.x*t.x - Dj.y*t.y;
                gi += Dj.x*t.y + Dj.y*t.x;
                float tx = t.x*w.x - t.y*w.y;
                float ty = t.x*w.y + t.y*w.x;
                t = make_float2(tx, ty);
            }
            Gp[h][dvi] = make_float2(gr, gi);
        }
        __syncthreads();
        if (tid < NDV) {
            float2 a = Gp[0][tid], b = Gp[1][tid];
            Gs[tid] = make_float2((a.x + b.x) * (1.0f/128.0f), (a.y + b.y) * (1.0f/128.0f));
        }
        __syncthreads();
        {
            int x0 = tid;
            float2 w = g_cs[x0];
            float2 t = g_cs[((-34) * x0) & 1023];
            float Ar[4] = {0.f,0.f,0.f,0.f}, Ai[4] = {0.f,0.f,0.f,0.f};
            #pragma unroll
            for (int dvi = 0; dvi < NDV; dvi++) {
                const int c = (dvi + 2) & 3;
                float2 G = Gs[dvi];
                Ar[c] += G.x*t.x - G.y*t.y;
                Ai[c] += G.x*t.y + G.y*t.x;
                float tx = t.x*w.x - t.y*w.y;
                float ty = t.x*w.y + t.y*w.x;
                t = make_float2(tx, ty);
            }
            float PRr = Ar[0] + Ar[2], PRi = Ai[0] + Ai[2];
            float MRr = Ar[0] - Ar[2], MRi = Ai[0] - Ai[2];
            float QRr = Ar[1] + Ar[3], QRi = Ai[1] + Ai[3];
            float DRr = Ar[1] - Ar[3], DRi = Ai[1] - Ai[3];
            g_D[n][br][du][x0      ] = make_float2(PRr + QRr, PRi + QRi);
            g_D[n][br][du][x0 + 256] = make_float2(MRr - DRi, MRi + DRr);
            g_D[n][br][du][x0 + 512] = make_float2(PRr - QRr, PRi - QRi);
            g_D[n][br][du][x0 + 768] = make_float2(MRr + DRi, MRi - DRr);
        }
    }
    grid_bar();

    // ===== phase 4: synthesis (du-pair packed, radix-2 in y) + outputs (512 units) =====
    {
        unsigned long long (*twx)[17] = (unsigned long long(*)[17])smbuf;           // 17408 B
        unsigned long long (*twy)[17] = (unsigned long long(*)[17])(smbuf + 17408); // 17408 B
        const size_t plane = (size_t)NB * HH * WW;
        for (int wi = bid; wi < 512; wi += NBLK) {
            int xs = wi & 31;
            int yq = (wi >> 5) & 3;
            int bz = wi >> 7;
            int n = bz >> 1, br = bz & 1;
            __syncthreads();                  // smem reuse across iterations
            for (int idx = tid; idx < 128*17; idx += 256) {
                int yp = idx / 17, p = idx % 17;
                int y = yq*128 + yp;
                float2 c0 = g_cs[((2*p+1) * y) & 1023];
                float2 c1 = g_cs[((2*p+2) * y) & 1023];
                twx[yp][p] = pk2(c0.x, c1.x);
                twy[yp][p] = pk2(c0.y, c1.y);
            }
            int lane = tid & 31, warp = tid >> 5;
            int x = xs*32 + lane;
            float D0 = g_D[n][br][0][x].x;
            unsigned long long dcx2[17], dcy2[17];
            #pragma unroll
            for (int p = 0; p < 17; p++) {
                float2 t0 = g_D[n][br][2*p+1][x];
                float2 t1 = g_D[n][br][2*p+2][x];
                dcx2[p] = pk2( 2.f*t0.x,  2.f*t1.x);
                dcy2[p] = pk2(-2.f*t0.y, -2.f*t1.y);
            }
            __syncthreads();
            const size_t base = (size_t)n * HH * WW;
            for (int yy = 0; yy < 16; yy++) {
                int yp = warp*16 + yy;
                int y  = yq*128 + yp;
                unsigned long long acc = pk2(0.f, D0);
                #pragma unroll
                for (int p = 0; p < 17; p++) {
                    acc = fma2(dcx2[p], twx[yp][p], acc);
                    acc = fma2(dcy2[p], twy[yp][p], acc);
                }
                float Ilo, Ihi;
                upk2(acc, Ilo, Ihi);
                float Ia = Ihi + Ilo;
                float Ib = Ihi - Ilo;
                size_t oa = base + (size_t)y * WW + x;
                size_t ob = oa + (size_t)512 * WW;
                if (br == 0) {
                    float IamX = 1.0404f * Ia, IbmX = 1.0404f * Ib;
                    out[oa]           = 1.f/(1.f + expf(-50.f*(Ia   - 0.225f)));
                    out[ob]           = 1.f/(1.f + expf(-50.f*(Ib   - 0.225f)));
                    out[2*plane + oa] = 1.f/(1.f + expf(-50.f*(IamX - 0.225f)));
                    out[2*plane + ob] = 1.f/(1.f + expf(-50.f*(IbmX - 0.225f)));
                    out[3*plane + oa] = Ia;
                    out[3*plane + ob] = Ib;
                    out[5*plane + oa] = IamX;
                    out[5*plane + ob] = IbmX;
                } else {
                    float IamN = 0.9604f * Ia, IbmN = 0.9604f * Ib;
                    out[plane   + oa] = 1.f/(1.f + expf(-50.f*(IamN - 0.225f)));
                    out[plane   + ob] = 1.f/(1.f + expf(-50.f*(IbmN - 0.225f)));
                    out[4*plane + oa] = IamN;
                    out[4*plane + ob] = IbmN;
                }
            }
        }
    }
}

// ---------------- launch (1 kernel) ----------------
extern "C" void kernel_launch(void* const* d_in, const int* in_sizes, int n_in,
                              void* d_out, int out_size) {
    const float* mask = (const float*)d_in[0];
    const float* fr   = (const float*)d_in[1];
    const float* fi   = (const float*)d_in[2];
    const float* dr   = (const float*)d_in[3];
    const float* di   = (const float*)d_in[4];
    const float* fs   = (const float*)d_in[5];
    const float* ds   = (const float*)d_in[6];
    float* out = (float*)d_out;

    k_all<<<NBLK, 256>>>(mask, fr, fi, dr, di, fs, ds, out);
}

// round 16
// speedup vs baseline: 1.4309x; 1.4309x over previous
#include <cuda_runtime.h>
#include <math.h>

#define HH 1024
#define WW 1024
#define NB 2
#define KK 24   // number of SOCS kernels
#define KD 35   // kernel spatial size / cropped spectrum size
#define FC 17   // center offset: frequency f = index - 17
#define U2 18   // u-pairs
#define UH 9    // u-pairs per thread-half
#define NS 128  // x-sample points (x = 8j)
#define NDV 69  // dv = -34..34
#define NBLK 148

// ---------------- scratch (static __device__, no allocation) ----------------
__device__ float2 g_cs[1024];                 // e^{+2pi i t/1024}
__device__ float2 g_T[NB][KD][HH];            // row DFT, transposed (j2-major)
__device__ float2 g_spec[NB][KD][KD];         // cropped spectrum (1/(H*W) folded)
__device__ float  g_Dj[NB][2][KD][NS][2];     // D at 128 x-samples (atomic accum)
__device__ float2 g_D[NB][2][KD][WW];         // cross-spectral density over du
__device__ unsigned g_barcnt;                 // grid barrier (zero-init; self-resetting)
__device__ unsigned g_bargen;                 // monotonic generation (replay-safe)

// ---------------- f32x2 packed helpers (Blackwell) ----------------
__device__ __forceinline__ unsigned long long pk2(float lo, float hi) {
    unsigned long long r;
    asm("mov.b64 %0, {%1, %2};" : "=l"(r) : "f"(lo), "f"(hi));
    return r;
}
__device__ __forceinline__ unsigned long long fma2(unsigned long long a, unsigned long long b, unsigned long long c) {
    unsigned long long d;
    asm("fma.rn.f32x2 %0, %1, %2, %3;" : "=l"(d) : "l"(a), "l"(b), "l"(c));
    return d;
}
__device__ __forceinline__ void upk2(unsigned long long v, float& lo, float& hi) {
    asm("mov.b64 {%0, %1}, %2;" : "=f"(lo), "=f"(hi) : "l"(v));
}
__device__ __forceinline__ float2 twd(int t) {
    float s, c;
    sincospif((float)(t & 1023) / 512.0f, &s, &c);
    return make_float2(c, s);
}

// ---------------- grid barrier (all NBLK blocks resident) ----------------
__device__ __forceinline__ void grid_bar() {
    __syncthreads();
    if (threadIdx.x == 0) {
        __threadfence();                                  // release prior global writes
        unsigned gen = *((volatile unsigned*)&g_bargen);  // read BEFORE arriving
        unsigned old = atomicAdd(&g_barcnt, 1u);
        if (old == NBLK - 1u) {
            *((volatile unsigned*)&g_barcnt) = 0u;
            __threadfence();
            atomicAdd(&g_bargen, 1u);
        } else {
            while (*((volatile unsigned*)&g_bargen) == gen) __nanosleep(64);
        }
        __threadfence();                                  // acquire
    }
    __syncthreads();
}

// ---------------- stage 1: fused avepool3+sigmoid + row DFT (+ table + zero g_Dj) ----------------
__global__ void __launch_bounds__(256) k_rowdft(const float* __restrict__ mask) {
    int yb = blockIdx.x;
    int n  = blockIdx.y;
    int tid = threadIdx.x;
    if (yb < 140 && n == 0) {                 // zero g_Dj: 140 blocks x 256 floats = 35840
        float* djf = &g_Dj[0][0][0][0][0];
        djf[yb*256 + tid] = 0.f;
    }
    if (yb == 256) {                          // twiddle-table block
        if (n == 0) {
            for (int t = tid; t < 1024; t += 256) {
                float s, c;
                sincospif((float)t / 512.0f, &s, &c);
                g_cs[t] = make_float2(c, s);
            }
        }
        return;
    }
    __shared__ float raw[6][WW];
    __shared__ float m_s[4][WW];
    const float* base = mask + (size_t)n * HH * WW;
    #pragma unroll
    for (int j = 0; j < 6; j++) {
        int gy = yb*4 - 1 + j;
        for (int x = tid; x < WW; x += 256)
            raw[j][x] = (gy >= 0 && gy < HH) ? base[(size_t)gy * WW + x] : 0.f;
    }
    __syncthreads();
    for (int x = tid; x < WW; x += 256) {
        float r0 = raw[0][x], r1 = raw[1][x], r2 = raw[2][x];
        float r3 = raw[3][x], r4 = raw[4][x], r5 = raw[5][x];
        raw[0][x] = r0 + r1 + r2;
        raw[1][x] = r1 + r2 + r3;
        raw[2][x] = r2 + r3 + r4;
        raw[3][x] = r3 + r4 + r5;
    }
    __syncthreads();
    for (int x = tid; x < WW; x += 256) {
        #pragma unroll
        for (int yy = 0; yy < 4; yy++) {
            float s = raw[yy][x];
            if (x > 0)    s += raw[yy][x-1];
            if (x < WW-1) s += raw[yy][x+1];
            float p = s * (1.0f/9.0f);
            m_s[yy][x] = 1.0f / (1.0f + expf(-4.0f * (p - 0.5f)));
        }
    }
    __syncthreads();
    int warp = tid >> 5, lane = tid & 31;
    for (int j2 = warp; j2 < KD; j2 += 8) {
        int a = FC - j2;                      // e^{-2pi i (j2-17) x/N} = e^{+2pi i a x/N}
        float2 t  = twd(a * lane);
        float2 st = twd(a * 32);              // warp-uniform step
        unsigned long long acc[4] = {0ull, 0ull, 0ull, 0ull};
        for (int i = 0; i < 32; i++) {
            int x = lane + 32*i;
            unsigned long long t2 = pk2(t.x, t.y);
            #pragma unroll
            for (int yy = 0; yy < 4; yy++) {
                float mv = m_s[yy][x];
                acc[yy] = fma2(pk2(mv, mv), t2, acc[yy]);
            }
            float tx = t.x*st.x - t.y*st.y;
            float ty = t.x*st.y + t.y*st.x;
            t = make_float2(tx, ty);
        }
        #pragma unroll
        for (int yy = 0; yy < 4; yy++) {
            float ar, ai;
            upk2(acc[yy], ar, ai);
            for (int o = 16; o; o >>= 1) {
                ar += __shfl_xor_sync(0xffffffffu, ar, o);
                ai += __shfl_xor_sync(0xffffffffu, ai, o);
            }
            if (lane == 0) g_T[n][j2][yb*4 + yy] = make_float2(ar, ai);
        }
    }
}

// ---------------- Gram helper (sampled) ----------------
template <int DU0, int DW>
__device__ __forceinline__ void gram_s(const unsigned long long* Ru, float s,
                                       float* dj, int j) {
    unsigned long long accX[DW], accY[DW];
    #pragma unroll
    for (int q = 0; q < DW; q++) { accX[q] = 0ull; accY[q] = 0ull; }
    #pragma unroll
    for (int u = 0; u < KD; u++) {
        float rx, ry;
        upk2(Ru[u], rx, ry);
        float ax = s * rx, ay = s * ry;
        unsigned long long axy  = pk2(ax, ay);
        unsigned long long aynx = pk2(ay, -ax);
        #pragma unroll
        for (int q = 0; q < DW; q++) {
            if (DU0 + q <= u) {
                unsigned long long bxy = Ru[u - DU0 - q];
                accX[q] = fma2(axy,  bxy, accX[q]);
                accY[q] = fma2(aynx, bxy, accY[q]);
            }
        }
    }
    #pragma unroll
    for (int q = 0; q < DW; q++) {
        float x0, x1, y0, y1;
        upk2(accX[q], x0, x1);
        upk2(accY[q], y0, y1);
        atomicAdd(&dj[(DU0 + q) * NS * 2 + j * 2 + 0], x0 + x1);
        atomicAdd(&dj[(DU0 + q) * NS * 2 + j * 2 + 1], y0 + y1);
    }
}

// ---------------- stage 2: fused coldft -> mid (R+Gram) -> DsynG, one kernel ----------------
__global__ void __launch_bounds__(256) k_mid3(
    const float* __restrict__ fr, const float* __restrict__ fi,
    const float* __restrict__ dr, const float* __restrict__ di,
    const float* __restrict__ fs, const float* __restrict__ ds)
{
    __shared__ __align__(16) char smbuf[46336];
    int tid = threadIdx.x;
    int bid = blockIdx.x;

    // ----- phase A: column DFT (70 units) -----
    if (bid < 70) {
        float2* Ts = (float2*)smbuf;          // 8192 B
        int j2 = bid % KD, n = bid / KD;
        for (int i = tid; i < HH; i += 256) Ts[i] = g_T[n][j2][i];
        __syncthreads();
        int warp = tid >> 5, lane = tid & 31;
        const float norm = 1.0f / (1024.0f * 1024.0f);
        for (int j1 = warp; j1 < KD; j1 += 8) {
            int a = FC - j1;
            float2 t  = g_cs[(a * lane) & 1023];
            float2 st = g_cs[(a * 32)   & 1023];
            float ar = 0.f, ai = 0.f;
            for (int i = 0; i < 32; i++) {
                float2 T = Ts[lane + 32*i];
                ar += T.x*t.x - T.y*t.y;
                ai += T.x*t.y + T.y*t.x;
                float tx = t.x*st.x - t.y*st.y;
                float ty = t.x*st.y + t.y*st.x;
                t = make_float2(tx, ty);
            }
            for (int o = 16; o; o >>= 1) {
                ar += __shfl_xor_sync(0xffffffffu, ar, o);
                ai += __shfl_xor_sync(0xffffffffu, ai, o);
            }
            if (lane == 0) g_spec[n][j1][j2] = make_float2(ar * norm, ai * norm);
        }
    }
    grid_bar();

    // ----- phase B: R-at-samples + Gram + atomic D_j (96 units) -----
    if (bid < 96) {
        float4 (*Bs)[U2] = (float4(*)[U2])smbuf;                 // 10080 B
        float2 (*Rs)[NS] = (float2(*)[NS])(smbuf + 10240);       // 35840 B
        int k   = bid % KK;
        int nbr = bid / KK; int n = nbr >> 1, br = nbr & 1;
        const float* krp = (br == 0) ? fr : dr;
        const float* kip = (br == 0) ? fi : di;
        float s = ((br == 0) ? fs : ds)[k];
        for (int i = tid; i < KD*U2; i += 256) {
            int u2 = i / KD, v = i % KD;
            int u0 = 2*u2, u1 = u0 + 1;
            float2 A0 = g_spec[n][u0][v];
            float Kr = krp[(k*KD + u0)*KD + v];
            float Ki = kip[(k*KD + u0)*KD + v];
            float b0x = A0.x*Kr - A0.y*Ki, b0y = A0.x*Ki + A0.y*Kr;
            float b1x = 0.f, b1y = 0.f;
            if (u1 < KD) {
                float2 A1 = g_spec[n][u1][v];
                float Kr1 = krp[(k*KD + u1)*KD + v];
                float Ki1 = kip[(k*KD + u1)*KD + v];
                b1x = A1.x*Kr1 - A1.y*Ki1; b1y = A1.x*Ki1 + A1.y*Kr1;
            }
            Bs[v][u2] = make_float4(b0x, b1x, b0y, b1y);
        }
        __syncthreads();
        int j = tid & 127, h = tid >> 7;
        {
            float2 w = g_cs[(8 * j) & 1023];
            float2 t = make_float2(1.f, 0.f);
            unsigned long long aR[UH], aI[UH];
            #pragma unroll
            for (int uu = 0; uu < UH; uu++) { aR[uu] = 0ull; aI[uu] = 0ull; }
            #pragma unroll
            for (int v = 0; v < KD; v++) {
                unsigned long long pxx = pk2(t.x,  t.x);
                unsigned long long pyy = pk2(t.y,  t.y);
                unsigned long long nyy = pk2(-t.y, -t.y);
                #pragma unroll
                for (int uu = 0; uu < UH; uu++) {
                    float4 b = Bs[v][h*UH + uu];
                    unsigned long long bx = pk2(b.x, b.y);
                    unsigned long long by = pk2(b.z, b.w);
                    aR[uu] = fma2(bx, pxx, aR[uu]);
                    aR[uu] = fma2(by, nyy, aR[uu]);
                    aI[uu] = fma2(bx, pyy, aI[uu]);
                    aI[uu] = fma2(by, pxx, aI[uu]);
                }
                float tx = t.x*w.x - t.y*w.y;
                float ty = t.x*w.y + t.y*w.x;
                t = make_float2(tx, ty);
            }
            #pragma unroll
            for (int uu = 0; uu < UH; uu++) {
                int u0 = 2*(h*UH + uu);
                float r0, r1, i0, i1;
                upk2(aR[uu], r0, r1);
                upk2(aI[uu], i0, i1);
                Rs[u0][j] = make_float2(r0, i0);
                if (u0 + 1 < KD) Rs[u0+1][j] = make_float2(r1, i1);
            }
        }
        __syncthreads();
        unsigned long long Ru[KD];
        #pragma unroll
        for (int u = 0; u < KD; u++)
            Ru[u] = *reinterpret_cast<const unsigned long long*>(&Rs[u][j]);
        float* dj = &g_Dj[n][br][0][0][0];
        if (h == 0) gram_s<0, 18>(Ru, s, dj, j);
        else        gram_s<18, 17>(Ru, s, dj, j);
    }
    grid_bar();

    // ----- phase C: Dj -> G (radix-2 in j) -> D (radix-4 in x) (140 units) -----
    if (bid < 140) {
        float2* Ds = (float2*)smbuf;                              // 1024 B
        float2 (*Gp)[NDV] = (float2(*)[NDV])(smbuf + 1024);       // 1104 B
        float2* Gs = (float2*)(smbuf + 1024 + 1104 + 8);          // 552 B
        int du  = bid % KD;
        int nbr = bid / KD; int n = nbr >> 1, br = nbr & 1;
        if (tid < NS) {
            const float* djp = &g_Dj[n][br][du][tid][0];
            Ds[tid] = make_float2(djp[0], djp[1]);
        }
        __syncthreads();
        if (tid < 2*NDV) {
            int dvi = (tid < NDV) ? tid : tid - NDV;
            int h   = (tid < NDV) ? 0 : 1;
            int dv  = dvi - 34;
            float2 w = g_cs[(-8 * dv) & 1023];
            float2 t = make_float2(((dv & 1) && h) ? -1.f : 1.f, 0.f);
            float gr = 0.f, gi = 0.f;
            #pragma unroll
            for (int j0 = 0; j0 < 64; j0++) {
                float2 Dj = Ds[j0 + 64*h];
                gr += Dj.x*t.x - Dj.y*t.y;
                gi += Dj.x*t.y + Dj.y*t.x;
                float tx = t.x*w.x - t.y*w.y;
                float ty = t.x*w.y + t.y*w.x;
                t = make_float2(tx, ty);
            }
            Gp[h][dvi] = make_float2(gr, gi);
        }
        __syncthreads();
        if (tid < NDV) {
            float2 a = Gp[0][tid], b = Gp[1][tid];
            Gs[tid] = make_float2((a.x + b.x) * (1.0f/128.0f), (a.y + b.y) * (1.0f/128.0f));
        }
        __syncthreads();
        {
            int x0 = tid;
            float2 w = g_cs[x0];
            float2 t = g_cs[((-34) * x0) & 1023];
            float Ar[4] = {0.f,0.f,0.f,0.f}, Ai[4] = {0.f,0.f,0.f,0.f};
            #pragma unroll
            for (int dvi = 0; dvi < NDV; dvi++) {
                const int c = (dvi + 2) & 3;
                float2 G = Gs[dvi];
                Ar[c] += G.x*t.x - G.y*t.y;
                Ai[c] += G.x*t.y + G.y*t.x;
                float tx = t.x*w.x - t.y*w.y;
                float ty = t.x*w.y + t.y*w.x;
                t = make_float2(tx, ty);
            }
            float PRr = Ar[0] + Ar[2], PRi = Ai[0] + Ai[2];
            float MRr = Ar[0] - Ar[2], MRi = Ai[0] - Ai[2];
            float QRr = Ar[1] + Ar[3], QRi = Ai[1] + Ai[3];
            float DRr = Ar[1] - Ar[3], DRi = Ai[1] - Ai[3];
            g_D[n][br][du][x0      ] = make_float2(PRr + QRr, PRi + QRi);
            g_D[n][br][du][x0 + 256] = make_float2(MRr - DRi, MRi + DRr);
            g_D[n][br][du][x0 + 512] = make_float2(PRr - QRr, PRi - QRi);
            g_D[n][br][du][x0 + 768] = make_float2(MRr + DRi, MRi - DRr);
        }
    }
}

// ---------------- stage 3: synthesis (du-pair packed, radix-2 in y) + outputs ----------------
__global__ void __launch_bounds__(256) k_final(float* __restrict__ out) {
    __shared__ unsigned long long twx[128][17];
    __shared__ unsigned long long twy[128][17];
    int xs = blockIdx.x;                     // 32-wide x strip
    int yq = blockIdx.y;                     // 0..3 (128 rows each, y in [0,512))
    int bz = blockIdx.z;                     // n(2) x br(2)
    int n = bz >> 1, br = bz & 1;
    int tid = threadIdx.x;
    for (int idx = tid; idx < 128*17; idx += 256) {
        int yp = idx / 17, p = idx % 17;
        int y = yq*128 + yp;
        float2 c0 = g_cs[((2*p+1) * y) & 1023];
        float2 c1 = g_cs[((2*p+2) * y) & 1023];
        twx[yp][p] = pk2(c0.x, c1.x);
        twy[yp][p] = pk2(c0.y, c1.y);
    }
    int lane = tid & 31, warp = tid >> 5;
    int x = xs*32 + lane;
    float D0 = g_D[n][br][0][x].x;           // D[0] is real
    unsigned long long dcx2[17], dcy2[17];
    #pragma unroll
    for (int p = 0; p < 17; p++) {
        float2 t0 = g_D[n][br][2*p+1][x];    // odd du -> lo
        float2 t1 = g_D[n][br][2*p+2][x];    // even du -> hi
        dcx2[p] = pk2( 2.f*t0.x,  2.f*t1.x);
        dcy2[p] = pk2(-2.f*t0.y, -2.f*t1.y);
    }
    __syncthreads();

    const size_t plane = (size_t)NB * HH * WW;
    const size_t base  = (size_t)n * HH * WW;
    for (int yy = 0; yy < 16; yy++) {
        int yp = warp*16 + yy;
        int y  = yq*128 + yp;                // in [0,512)
        unsigned long long acc = pk2(0.f, D0);
        #pragma unroll
        for (int p = 0; p < 17; p++) {
            acc = fma2(dcx2[p], twx[yp][p], acc);
            acc = fma2(dcy2[p], twy[yp][p], acc);
        }
        float Ilo, Ihi;
        upk2(acc, Ilo, Ihi);
        float Ia = Ihi + Ilo;                // I(y)
        float Ib = Ihi - Ilo;                // I(y+512)
        size_t oa = base + (size_t)y * WW + x;
        size_t ob = oa + (size_t)512 * WW;
        if (br == 0) {
            float IamX = 1.0404f * Ia, IbmX = 1.0404f * Ib;
            out[oa]           = 1.f/(1.f + expf(-50.f*(Ia   - 0.225f)));
            out[ob]           = 1.f/(1.f + expf(-50.f*(Ib   - 0.225f)));
            out[2*plane + oa] = 1.f/(1.f + expf(-50.f*(IamX - 0.225f)));
            out[2*plane + ob] = 1.f/(1.f + expf(-50.f*(IbmX - 0.225f)));
            out[3*plane + oa] = Ia;
            out[3*plane + ob] = Ib;
            out[5*plane + oa] = IamX;
            out[5*plane + ob] = IbmX;
        } else {
            float IamN = 0.9604f * Ia, IbmN = 0.9604f * Ib;
            out[plane   + oa] = 1.f/(1.f + expf(-50.f*(IamN - 0.225f)));
            out[plane   + ob] = 1.f/(1.f + expf(-50.f*(IbmN - 0.225f)));
            out[4*plane + oa] = IamN;
            out[4*plane + ob] = IbmN;
        }
    }
}

// ---------------- launch (3 kernels) ----------------
extern "C" void kernel_launch(void* const* d_in, const int* in_sizes, int n_in,
                              void* d_out, int out_size) {
    const float* mask = (const float*)d_in[0];
    const float* fr   = (const float*)d_in[1];
    const float* fi   = (const float*)d_in[2];
    const float* dr   = (const float*)d_in[3];
    const float* di   = (const float*)d_in[4];
    const float* fs   = (const float*)d_in[5];
    const float* ds   = (const float*)d_in[6];
    float* out = (float*)d_out;

    k_rowdft <<<dim3(257, NB), 256>>>(mask);
    k_mid3   <<<NBLK, 256>>>(fr, fi, dr, di, fs, ds);
    k_final  <<<dim3(32, 4, 4), 256>>>(out);
}

// round 17
// speedup vs baseline: 1.4938x; 1.0440x over previous
#include <cuda_runtime.h>
#include <math.h>

#define HH 1024
#define WW 1024
#define NB 2
#define KK 24   // number of SOCS kernels
#define KD 35   // kernel spatial size / cropped spectrum size
#define FC 17   // center offset: frequency f = index - 17
#define U2 18   // u-pairs
#define UH 9    // u-pairs per thread-half
#define NS 128  // x-sample points (x = 8j)
#define NDV 69  // dv = -34..34
#define NBLK 148

// ---------------- scratch (static __device__, no allocation) ----------------
__device__ float2 g_cs[1024];                 // e^{+2pi i t/1024}
__device__ float2 g_T[NB][KD][HH];            // row DFT, transposed (j2-major)
__device__ float2 g_spec[NB][KD][KD];         // cropped spectrum (1/(H*W) folded)
__device__ float  g_Dj[NB][2][KD][NS][2];     // D at 128 x-samples (atomic accum)
__device__ float2 g_D[NB][2][KD][WW];         // cross-spectral density over du
__device__ unsigned g_barcnt;                 // grid barrier (zero-init; self-resetting)
__device__ unsigned g_bargen;                 // monotonic generation (replay-safe)

// ---------------- f32x2 packed helpers (Blackwell) ----------------
__device__ __forceinline__ unsigned long long pk2(float lo, float hi) {
    unsigned long long r;
    asm("mov.b64 %0, {%1, %2};" : "=l"(r) : "f"(lo), "f"(hi));
    return r;
}
__device__ __forceinline__ unsigned long long fma2(unsigned long long a, unsigned long long b, unsigned long long c) {
    unsigned long long d;
    asm("fma.rn.f32x2 %0, %1, %2, %3;" : "=l"(d) : "l"(a), "l"(b), "l"(c));
    return d;
}
__device__ __forceinline__ void upk2(unsigned long long v, float& lo, float& hi) {
    asm("mov.b64 {%0, %1}, %2;" : "=f"(lo), "=f"(hi) : "l"(v));
}
__device__ __forceinline__ float2 twd(int t) {
    float s, c;
    sincospif((float)(t & 1023) / 512.0f, &s, &c);
    return make_float2(c, s);
}

// MUFU-free sigmoid(4(p-1/2)) = 0.5 + 0.5*tanh(w), w = 2p-1 in [-1,1].
// tanh via Pade [5/4] (abs err ~5e-8 on [-1,1]); reciprocal via linear seed + 3 Newton.
__device__ __forceinline__ float sigmoid4(float p) {
    float w = 2.0f*p - 1.0f;
    float u = w*w;
    float num = (u + 105.0f)*u + 945.0f;
    float den = (15.0f*u + 420.0f)*u + 945.0f;       // in [945, 1380]
    float y = fmaf(-7.668124e-7f, den, 1.7670992e-3f); // linear minimax seed of 1/den
    y = y * (2.0f - den*y);
    y = y * (2.0f - den*y);
    y = y * (2.0f - den*y);
    return fmaf(0.5f*w*num, y, 0.5f);
}

// ---------------- grid barrier (all NBLK blocks resident) ----------------
__device__ __forceinline__ void grid_bar() {
    __syncthreads();
    if (threadIdx.x == 0) {
        __threadfence();                                  // release prior global writes
        unsigned gen = *((volatile unsigned*)&g_bargen);  // read BEFORE arriving
        unsigned old = atomicAdd(&g_barcnt, 1u);
        if (old == NBLK - 1u) {
            *((volatile unsigned*)&g_barcnt) = 0u;
            __threadfence();
            atomicAdd(&g_bargen, 1u);
        } else {
            while (*((volatile unsigned*)&g_bargen) == gen) __nanosleep(64);
        }
        __threadfence();                                  // acquire
    }
    __syncthreads();
}

// ---------------- stage 1: pool+sigmoid (poly) + radix-4 row DFT ----------------
__global__ void __launch_bounds__(256) k_rowdft(const float* __restrict__ mask) {
    int yb = blockIdx.x;
    int n  = blockIdx.y;
    int tid = threadIdx.x;
    if (yb < 140 && n == 0) {                 // zero g_Dj: 140 blocks x 256 floats = 35840
        float* djf = &g_Dj[0][0][0][0][0];
        djf[yb*256 + tid] = 0.f;
    }
    if (yb == 256) {                          // twiddle-table block
        if (n == 0) {
            for (int t = tid; t < 1024; t += 256) {
                float s, c;
                sincospif((float)t / 512.0f, &s, &c);
                g_cs[t] = make_float2(c, s);
            }
        }
        return;
    }
    __shared__ float raw[6][WW];              // reused for class sums after pooling
    __shared__ float m_s[4][WW];
    const float* base = mask + (size_t)n * HH * WW;
    #pragma unroll
    for (int j = 0; j < 6; j++) {
        int gy = yb*4 - 1 + j;
        for (int x = tid; x < WW; x += 256)
            raw[j][x] = (gy >= 0 && gy < HH) ? base[(size_t)gy * WW + x] : 0.f;
    }
    __syncthreads();
    for (int x = tid; x < WW; x += 256) {
        float r0 = raw[0][x], r1 = raw[1][x], r2 = raw[2][x];
        float r3 = raw[3][x], r4 = raw[4][x], r5 = raw[5][x];
        raw[0][x] = r0 + r1 + r2;
        raw[1][x] = r1 + r2 + r3;
        raw[2][x] = r2 + r3 + r4;
        raw[3][x] = r3 + r4 + r5;
    }
    __syncthreads();
    for (int x = tid; x < WW; x += 256) {
        #pragma unroll
        for (int yy = 0; yy < 4; yy++) {
            float s = raw[yy][x];
            if (x > 0)    s += raw[yy][x-1];
            if (x < WW-1) s += raw[yy][x+1];
            float p = s * (1.0f/9.0f);
            m_s[yy][x] = sigmoid4(p);         // MUFU-free
        }
    }
    __syncthreads();
    // radix-4 class sums over x-quarters: cls[c][row][x0], c: 0=E+O, 1=A, 2=E-O, 3=B
    float* cls = &raw[0][0];                  // 4*4*256 = 4096 floats (fits in raw)
    {
        int x0 = tid;                         // 256 threads = 256 x0
        #pragma unroll
        for (int yy = 0; yy < 4; yy++) {
            float m0 = m_s[yy][x0];
            float m1 = m_s[yy][x0 + 256];
            float m2 = m_s[yy][x0 + 512];
            float m3 = m_s[yy][x0 + 768];
            float E = m0 + m2, O = m1 + m3;
            cls[0*1024 + yy*256 + x0] = E + O;
            cls[1*1024 + yy*256 + x0] = m0 - m2;     // A
            cls[2*1024 + yy*256 + x0] = E - O;
            cls[3*1024 + yy*256 + x0] = m1 - m3;     // B
        }
    }
    __syncthreads();
    int warp = tid >> 5, lane = tid & 31;
    for (int j2 = warp; j2 < KD; j2 += 8) {
        int a = FC - j2;                      // e^{+2pi i a x/N}
        int c = a & 3;                        // a mod 4 (two's complement ok)
        float2 t  = twd(a * lane);
        float2 st = twd(a * 32);              // warp-uniform step
        unsigned long long acc[4] = {0ull, 0ull, 0ull, 0ull};
        for (int i = 0; i < 8; i++) {
            int x0 = lane + 32*i;
            unsigned long long t2 = pk2(t.x, t.y);
            if ((c & 1) == 0) {
                const float* cb = cls + (c == 0 ? 0 : 2*1024) + x0;
                #pragma unroll
                for (int yy = 0; yy < 4; yy++) {
                    float v = cb[yy*256];
                    acc[yy] = fma2(pk2(v, v), t2, acc[yy]);
                }
            } else {
                // (A + i*s*B)(tx + i ty), s=+1 for c=1, s=-1 for c=3
                unsigned long long t2b = (c == 1) ? pk2(-t.y, t.x) : pk2(t.y, -t.x);
                #pragma unroll
                for (int yy = 0; yy < 4; yy++) {
                    float A = cls[1*1024 + yy*256 + x0];
                    float B = cls[3*1024 + yy*256 + x0];
                    acc[yy] = fma2(pk2(A, A), t2,  acc[yy]);
                    acc[yy] = fma2(pk2(B, B), t2b, acc[yy]);
                }
            }
            float tx = t.x*st.x - t.y*st.y;   // t *= st
            float ty = t.x*st.y + t.y*st.x;
            t = make_float2(tx, ty);
        }
        #pragma unroll
        for (int yy = 0; yy < 4; yy++) {
            float ar, ai;
            upk2(acc[yy], ar, ai);
            for (int o = 16; o; o >>= 1) {
                ar += __shfl_xor_sync(0xffffffffu, ar, o);
                ai += __shfl_xor_sync(0xffffffffu, ai, o);
            }
            if (lane == 0) g_T[n][j2][yb*4 + yy] = make_float2(ar, ai);
        }
    }
}

// ---------------- Gram helper (sampled) ----------------
template <int DU0, int DW>
__device__ __forceinline__ void gram_s(const unsigned long long* Ru, float s,
                                       float* dj, int j) {
    unsigned long long accX[DW], accY[DW];
    #pragma unroll
    for (int q = 0; q < DW; q++) { accX[q] = 0ull; accY[q] = 0ull; }
    #pragma unroll
    for (int u = 0; u < KD; u++) {
        float rx, ry;
        upk2(Ru[u], rx, ry);
        float ax = s * rx, ay = s * ry;
        unsigned long long axy  = pk2(ax, ay);
        unsigned long long aynx = pk2(ay, -ax);
        #pragma unroll
        for (int q = 0; q < DW; q++) {
            if (DU0 + q <= u) {
                unsigned long long bxy = Ru[u - DU0 - q];
                accX[q] = fma2(axy,  bxy, accX[q]);
                accY[q] = fma2(aynx, bxy, accY[q]);
            }
        }
    }
    #pragma unroll
    for (int q = 0; q < DW; q++) {
        float x0, x1, y0, y1;
        upk2(accX[q], x0, x1);
        upk2(accY[q], y0, y1);
        atomicAdd(&dj[(DU0 + q) * NS * 2 + j * 2 + 0], x0 + x1);
        atomicAdd(&dj[(DU0 + q) * NS * 2 + j * 2 + 1], y0 + y1);
    }
}

// ---------------- stage 2: fused coldft -> mid (R+Gram) -> DsynG, one kernel ----------------
__global__ void __launch_bounds__(256) k_mid3(
    const float* __restrict__ fr, const float* __restrict__ fi,
    const float* __restrict__ dr, const float* __restrict__ di,
    const float* __restrict__ fs, const float* __restrict__ ds)
{
    __shared__ __align__(16) char smbuf[46336];
    int tid = threadIdx.x;
    int bid = blockIdx.x;

    // ----- phase A: column DFT (70 units) -----
    if (bid < 70) {
        float2* Ts = (float2*)smbuf;          // 8192 B
        int j2 = bid % KD, n = bid / KD;
        for (int i = tid; i < HH; i += 256) Ts[i] = g_T[n][j2][i];
        __syncthreads();
        int warp = tid >> 5, lane = tid & 31;
        const float norm = 1.0f / (1024.0f * 1024.0f);
        for (int j1 = warp; j1 < KD; j1 += 8) {
            int a = FC - j1;
            float2 t  = g_cs[(a * lane) & 1023];
            float2 st = g_cs[(a * 32)   & 1023];
            float ar = 0.f, ai = 0.f;
            for (int i = 0; i < 32; i++) {
                float2 T = Ts[lane + 32*i];
                ar += T.x*t.x - T.y*t.y;
                ai += T.x*t.y + T.y*t.x;
                float tx = t.x*st.x - t.y*st.y;
                float ty = t.x*st.y + t.y*st.x;
                t = make_float2(tx, ty);
            }
            for (int o = 16; o; o >>= 1) {
                ar += __shfl_xor_sync(0xffffffffu, ar, o);
                ai += __shfl_xor_sync(0xffffffffu, ai, o);
            }
            if (lane == 0) g_spec[n][j1][j2] = make_float2(ar * norm, ai * norm);
        }
    }
    grid_bar();

    // ----- phase B: R-at-samples + Gram + atomic D_j (96 units) -----
    if (bid < 96) {
        float4 (*Bs)[U2] = (float4(*)[U2])smbuf;                 // 10080 B
        float2 (*Rs)[NS] = (float2(*)[NS])(smbuf + 10240);       // 35840 B
        int k   = bid % KK;
        int nbr = bid / KK; int n = nbr >> 1, br = nbr & 1;
        const float* krp = (br == 0) ? fr : dr;
        const float* kip = (br == 0) ? fi : di;
        float s = ((br == 0) ? fs : ds)[k];
        for (int i = tid; i < KD*U2; i += 256) {
            int u2 = i / KD, v = i % KD;
            int u0 = 2*u2, u1 = u0 + 1;
            float2 A0 = g_spec[n][u0][v];
            float Kr = krp[(k*KD + u0)*KD + v];
            float Ki = kip[(k*KD + u0)*KD + v];
            float b0x = A0.x*Kr - A0.y*Ki, b0y = A0.x*Ki + A0.y*Kr;
            float b1x = 0.f, b1y = 0.f;
            if (u1 < KD) {
                float2 A1 = g_spec[n][u1][v];
                float Kr1 = krp[(k*KD + u1)*KD + v];
                float Ki1 = kip[(k*KD + u1)*KD + v];
                b1x = A1.x*Kr1 - A1.y*Ki1; b1y = A1.x*Ki1 + A1.y*Kr1;
            }
            Bs[v][u2] = make_float4(b0x, b1x, b0y, b1y);
        }
        __syncthreads();
        int j = tid & 127, h = tid >> 7;
        {
            float2 w = g_cs[(8 * j) & 1023];
            float2 t = make_float2(1.f, 0.f);
            unsigned long long aR[UH], aI[UH];
            #pragma unroll
            for (int uu = 0; uu < UH; uu++) { aR[uu] = 0ull; aI[uu] = 0ull; }
            #pragma unroll
            for (int v = 0; v < KD; v++) {
                unsigned long long pxx = pk2(t.x,  t.x);
                unsigned long long pyy = pk2(t.y,  t.y);
                unsigned long long nyy = pk2(-t.y, -t.y);
                #pragma unroll
                for (int uu = 0; uu < UH; uu++) {
                    float4 b = Bs[v][h*UH + uu];
                    unsigned long long bx = pk2(b.x, b.y);
                    unsigned long long by = pk2(b.z, b.w);
                    aR[uu] = fma2(bx, pxx, aR[uu]);
                    aR[uu] = fma2(by, nyy, aR[uu]);
                    aI[uu] = fma2(bx, pyy, aI[uu]);
                    aI[uu] = fma2(by, pxx, aI[uu]);
                }
                float tx = t.x*w.x - t.y*w.y;
                float ty = t.x*w.y + t.y*w.x;
                t = make_float2(tx, ty);
            }
            #pragma unroll
            for (int uu = 0; uu < UH; uu++) {
                int u0 = 2*(h*UH + uu);
                float r0, r1, i0, i1;
                upk2(aR[uu], r0, r1);
                upk2(aI[uu], i0, i1);
                Rs[u0][j] = make_float2(r0, i0);
                if (u0 + 1 < KD) Rs[u0+1][j] = make_float2(r1, i1);
            }
        }
        __syncthreads();
        unsigned long long Ru[KD];
        #pragma unroll
        for (int u = 0; u < KD; u++)
            Ru[u] = *reinterpret_cast<const unsigned long long*>(&Rs[u][j]);
        float* dj = &g_Dj[n][br][0][0][0];
        if (h == 0) gram_s<0, 18>(Ru, s, dj, j);
        else        gram_s<18, 17>(Ru, s, dj, j);
    }
    grid_bar();

    // ----- phase C: Dj -> G (radix-2 in j) -> D (radix-4 in x) (140 units) -----
    if (bid < 140) {
        float2* Ds = (float2*)smbuf;                              // 1024 B
        float2 (*Gp)[NDV] = (float2(*)[NDV])(smbuf + 1024);       // 1104 B
        float2* Gs = (float2*)(smbuf + 1024 + 1104 + 8);          // 552 B
        int du  = bid % KD;
        int nbr = bid / KD; int n = nbr >> 1, br = nbr & 1;
        if (tid < NS) {
            const float* djp = &g_Dj[n][br][du][tid][0];
            Ds[tid] = make_float2(djp[0], djp[1]);
        }
        __syncthreads();
        if (tid < 2*NDV) {
            int dvi = (tid < NDV) ? tid : tid - NDV;
            int h   = (tid < NDV) ? 0 : 1;
            int dv  = dvi - 34;
            float2 w = g_cs[(-8 * dv) & 1023];
            float2 t = make_float2(((dv & 1) && h) ? -1.f : 1.f, 0.f);
            float gr = 0.f, gi = 0.f;
            #pragma unroll
            for (int j0 = 0; j0 < 64; j0++) {
                float2 Dj = Ds[j0 + 64*h];
                gr += Dj.x*t.x - Dj.y*t.y;
                gi += Dj.x*t.y + Dj.y*t.x;
                float tx = t.x*w.x - t.y*w.y;
                float ty = t.x*w.y + t.y*w.x;
                t = make_float2(tx, ty);
            }
            Gp[h][dvi] = make_float2(gr, gi);
        }
        __syncthreads();
        if (tid < NDV) {
            float2 a = Gp[0][tid], b = Gp[1][tid];
            Gs[tid] = make_float2((a.x + b.x) * (1.0f/128.0f), (a.y + b.y) * (1.0f/128.0f));
        }
        __syncthreads();
        {
            int x0 = tid;
            float2 w = g_cs[x0];
            float2 t = g_cs[((-34) * x0) & 1023];
            float Ar[4] = {0.f,0.f,0.f,0.f}, Ai[4] = {0.f,0.f,0.f,0.f};
            #pragma unroll
            for (int dvi = 0; dvi < NDV; dvi++) {
                const int c = (dvi + 2) & 3;
                float2 G = Gs[dvi];
                Ar[c] += G.x*t.x - G.y*t.y;
                Ai[c] += G.x*t.y + G.y*t.x;
                float tx = t.x*w.x - t.y*w.y;
                float ty = t.x*w.y + t.y*w.x;
                t = make_float2(tx, ty);
            }
            float PRr = Ar[0] + Ar[2], PRi = Ai[0] + Ai[2];
            float MRr = Ar[0] - Ar[2], MRi = Ai[0] - Ai[2];
            float QRr = Ar[1] + Ar[3], QRi = Ai[1] + Ai[3];
            float DRr = Ar[1] - Ar[3], DRi = Ai[1] - Ai[3];
            g_D[n][br][du][x0      ] = make_float2(PRr + QRr, PRi + QRi);
            g_D[n][br][du][x0 + 256] = make_float2(MRr - DRi, MRi + DRr);
            g_D[n][br][du][x0 + 512] = make_float2(PRr - QRr, PRi - QRi);
            g_D[n][br][du][x0 + 768] = make_float2(MRr + DRi, MRi - DRr);
        }
    }
}

// ---------------- stage 3: synthesis (du-pair packed, radix-2 in y) + outputs ----------------
__global__ void __launch_bounds__(256) k_final(float* __restrict__ out) {
    __shared__ unsigned long long twx[128][17];
    __shared__ unsigned long long twy[128][17];
    int xs = blockIdx.x;                     // 32-wide x strip
    int yq = blockIdx.y;                     // 0..3 (128 rows each, y in [0,512))
    int bz = blockIdx.z;                     // n(2) x br(2)
    int n = bz >> 1, br = bz & 1;
    int tid = threadIdx.x;
    for (int idx = tid; idx < 128*17; idx += 256) {
        int yp = idx / 17, p = idx % 17;
        int y = yq*128 + yp;
        float2 c0 = g_cs[((2*p+1) * y) & 1023];
        float2 c1 = g_cs[((2*p+2) * y) & 1023];
        twx[yp][p] = pk2(c0.x, c1.x);
        twy[yp][p] = pk2(c0.y, c1.y);
    }
    int lane = tid & 31, warp = tid >> 5;
    int x = xs*32 + lane;
    float D0 = g_D[n][br][0][x].x;           // D[0] is real
    unsigned long long dcx2[17], dcy2[17];
    #pragma unroll
    for (int p = 0; p < 17; p++) {
        float2 t0 = g_D[n][br][2*p+1][x];    // odd du -> lo
        float2 t1 = g_D[n][br][2*p+2][x];    // even du -> hi
        dcx2[p] = pk2( 2.f*t0.x,  2.f*t1.x);
        dcy2[p] = pk2(-2.f*t0.y, -2.f*t1.y);
    }
    __syncthreads();

    const size_t plane = (size_t)NB * HH * WW;
    const size_t base  = (size_t)n * HH * WW;
    for (int yy = 0; yy < 16; yy++) {
        int yp = warp*16 + yy;
        int y  = yq*128 + yp;                // in [0,512)
        unsigned long long acc = pk2(0.f, D0);
        #pragma unroll
        for (int p = 0; p < 17; p++) {
            acc = fma2(dcx2[p], twx[yp][p], acc);
            acc = fma2(dcy2[p], twy[yp][p], acc);
        }
        float Ilo, Ihi;
        upk2(acc, Ilo, Ihi);
        float Ia = Ihi + Ilo;                // I(y)
        float Ib = Ihi - Ilo;                // I(y+512)
        size_t oa = base + (size_t)y * WW + x;
        size_t ob = oa + (size_t)512 * WW;
        if (br == 0) {
            float IamX = 1.0404f * Ia, IbmX = 1.0404f * Ib;
            out[oa]           = 1.f/(1.f + expf(-50.f*(Ia   - 0.225f)));
            out[ob]           = 1.f/(1.f + expf(-50.f*(Ib   - 0.225f)));
            out[2*plane + oa] = 1.f/(1.f + expf(-50.f*(IamX - 0.225f)));
            out[2*plane + ob] = 1.f/(1.f + expf(-50.f*(IbmX - 0.225f)));
            out[3*plane + oa] = Ia;
            out[3*plane + ob] = Ib;
            out[5*plane + oa] = IamX;
            out[5*plane + ob] = IbmX;
        } else {
            float IamN = 0.9604f * Ia, IbmN = 0.9604f * Ib;
            out[plane   + oa] = 1.f/(1.f + expf(-50.f*(IamN - 0.225f)));
            out[plane   + ob] = 1.f/(1.f + expf(-50.f*(IbmN - 0.225f)));
            out[4*plane + oa] = IamN;
            out[4*plane + ob] = IbmN;
        }
    }
}

// ---------------- launch (3 kernels) ----------------
extern "C" void kernel_launch(void* const* d_in, const int* in_sizes, int n_in,
                              void* d_out, int out_size) {
    const float* mask = (const float*)d_in[0];
    const float* fr   = (const float*)d_in[1];
    const float* fi   = (const float*)d_in[2];
    const float* dr   = (const float*)d_in[3];
    const float* di   = (const float*)d_in[4];
    const float* fs   = (const float*)d_in[5];
    const float* ds   = (const float*)d_in[6];
    float* out = (float*)d_out;

    k_rowdft <<<dim3(257, NB), 256>>>(mask);
    k_mid3   <<<NBLK, 256>>>(fr, fi, dr, di, fs, ds);
    k_final  <<<dim3(32, 4, 4), 256>>>(out);
}